// round 3
// baseline (speedup 1.0000x reference)
#include <cuda_runtime.h>
#include <cuda_bf16.h>
#include <cstdint>

#define S_LEN 2048
#define B_SZ  64
#define I_DIM 128
#define H_DIM 256
#define O_DIM 64
#define NROWS (S_LEN * B_SZ)   // 131072 rows, n = b*S + s

// Scratch (static device arrays: allocation-free rule).
// bufA: Z0 then T1 ; bufB: H0 then T2 ; bufC: Z1 ; bufD: H1 (outs)
__device__ float g_bufA[(size_t)NROWS * H_DIM];
__device__ float g_bufB[(size_t)NROWS * H_DIM];
__device__ float g_bufC[(size_t)NROWS * H_DIM];
__device__ float g_bufD[(size_t)NROWS * H_DIM];

// ---------------------------------------------------------------------------
// GEMM: C[M,N] = A[M,K] @ W[N,K]^T + b1[n] (+ b2[n])
// BM=128, BN=128, BK=16, TM=TN=8, 256 threads. M % 128 == 0, K % 16 == 0,
// N % 8 == 0 (N may be < BN; guarded).
// ---------------------------------------------------------------------------
__global__ __launch_bounds__(256) void sgemm_bias(
    const float* __restrict__ A, const float* __restrict__ W,
    const float* __restrict__ b1, const float* __restrict__ b2,
    float* __restrict__ C, int M, int N, int K)
{
    constexpr int BM = 128, BN = 128, BK = 16, TM = 8, TN = 8;
    __shared__ __align__(16) float As[BK][BM + 4];
    __shared__ __align__(16) float Ws[BK][BN + 4];

    const int tid = threadIdx.x;
    const int tx  = tid & 15;   // 0..15 -> n sub-tile
    const int ty  = tid >> 4;   // 0..15 -> m sub-tile
    const int m0  = blockIdx.y * BM;
    const int n0  = blockIdx.x * BN;

    float acc[TM][TN];
#pragma unroll
    for (int i = 0; i < TM; i++)
#pragma unroll
        for (int j = 0; j < TN; j++) acc[i][j] = 0.f;

    for (int k0 = 0; k0 < K; k0 += BK) {
        // Load A tile (128x16), transposed into As[k][m]
#pragma unroll
        for (int l = 0; l < 2; l++) {
            int idx = tid + l * 256;          // 0..511
            int r = idx >> 2;                 // 0..127
            int c = (idx & 3) << 2;           // 0,4,8,12
            float4 v = *reinterpret_cast<const float4*>(
                A + (size_t)(m0 + r) * K + k0 + c);
            As[c + 0][r] = v.x; As[c + 1][r] = v.y;
            As[c + 2][r] = v.z; As[c + 3][r] = v.w;
        }
        // Load W tile (128x16 rows of W[N,K]), transposed into Ws[k][n]
#pragma unroll
        for (int l = 0; l < 2; l++) {
            int idx = tid + l * 256;
            int r = idx >> 2;
            int c = (idx & 3) << 2;
            float4 v = make_float4(0.f, 0.f, 0.f, 0.f);
            if (n0 + r < N)
                v = *reinterpret_cast<const float4*>(
                    W + (size_t)(n0 + r) * K + k0 + c);
            Ws[c + 0][r] = v.x; Ws[c + 1][r] = v.y;
            Ws[c + 2][r] = v.z; Ws[c + 3][r] = v.w;
        }
        __syncthreads();

#pragma unroll
        for (int k = 0; k < BK; k++) {
            float rm[TM], rn[TN];
            *reinterpret_cast<float4*>(&rm[0]) =
                *reinterpret_cast<const float4*>(&As[k][ty * TM]);
            *reinterpret_cast<float4*>(&rm[4]) =
                *reinterpret_cast<const float4*>(&As[k][ty * TM + 4]);
            *reinterpret_cast<float4*>(&rn[0]) =
                *reinterpret_cast<const float4*>(&Ws[k][tx * TN]);
            *reinterpret_cast<float4*>(&rn[4]) =
                *reinterpret_cast<const float4*>(&Ws[k][tx * TN + 4]);
#pragma unroll
            for (int i = 0; i < TM; i++)
#pragma unroll
                for (int j = 0; j < TN; j++)
                    acc[i][j] = fmaf(rm[i], rn[j], acc[i][j]);
        }
        __syncthreads();
    }

    // Epilogue: bias add + store. N % TN == 0 -> whole 8-chunk in or out.
    const int gn0 = n0 + tx * TN;
    if (gn0 < N) {
        float bias[TN];
#pragma unroll
        for (int j = 0; j < TN; j++) {
            int gn = gn0 + j;
            bias[j] = b1[gn] + (b2 ? b2[gn] : 0.f);
        }
#pragma unroll
        for (int i = 0; i < TM; i++) {
            int gm = m0 + ty * TM + i;
            float4 o0, o1;
            o0.x = acc[i][0] + bias[0]; o0.y = acc[i][1] + bias[1];
            o0.z = acc[i][2] + bias[2]; o0.w = acc[i][3] + bias[3];
            o1.x = acc[i][4] + bias[4]; o1.y = acc[i][5] + bias[5];
            o1.z = acc[i][6] + bias[6]; o1.w = acc[i][7] + bias[7];
            *reinterpret_cast<float4*>(C + (size_t)gm * N + gn0)     = o0;
            *reinterpret_cast<float4*>(C + (size_t)gm * N + gn0 + 4) = o1;
        }
    }
}

// ---------------------------------------------------------------------------
// Recurrent scan: H[t] = tanh(Z[t] + W @ H[t-1]) for one batch element.
// Cluster of 2 CTAs per batch element. CTA rank r owns output rows
// [r*128, r*128+128), holds W rows in registers (64 floats/thread),
// exchanges its h-half with the peer via DSMEM each step.
// 512 threads: tid = kc*64 + ri ; kc in [0,8) -> k range [kc*32, kc*32+32),
// ri in [0,64) -> local rows {ri, ri+64}.
// Warp-uniform kc => h reads are whole-warp broadcast (conflict-free).
// ---------------------------------------------------------------------------
__global__ void __cluster_dims__(2, 1, 1) __launch_bounds__(512, 1)
scan_rnn(const float* __restrict__ Z, const float* __restrict__ Wr,
         float* __restrict__ Hout)
{
    __shared__ __align__(16) float h_buf[2][H_DIM];
    __shared__ float stage[128][9];   // pad 9 -> conflict-free STS/LDS

    const int tid = threadIdx.x;
    uint32_t rank_u;
    asm("mov.u32 %0, %%cluster_ctarank;" : "=r"(rank_u));
    const int rank  = (int)rank_u;
    const int batch = blockIdx.x >> 1;
    const int kc = tid >> 6;        // 0..7
    const int ri = tid & 63;        // 0..63
    const int row0 = rank * 128 + ri;
    const int row1 = row0 + 64;

    // Register-resident W chunk: rows {row0,row1}, k in [kc*32, kc*32+32)
    float w0[32], w1[32];
#pragma unroll
    for (int j = 0; j < 8; j++) {
        float4 a = *reinterpret_cast<const float4*>(
            Wr + (size_t)row0 * H_DIM + kc * 32 + j * 4);
        w0[j * 4 + 0] = a.x; w0[j * 4 + 1] = a.y;
        w0[j * 4 + 2] = a.z; w0[j * 4 + 3] = a.w;
        float4 b = *reinterpret_cast<const float4*>(
            Wr + (size_t)row1 * H_DIM + kc * 32 + j * 4);
        w1[j * 4 + 0] = b.x; w1[j * 4 + 1] = b.y;
        w1[j * 4 + 2] = b.z; w1[j * 4 + 3] = b.w;
    }

    if (tid < H_DIM) { h_buf[0][tid] = 0.f; h_buf[1][tid] = 0.f; }

    // Peer's h_buf base address (DSMEM)
    uint32_t hloc;
    {
        uint64_t t64;
        asm("cvta.to.shared.u64 %0, %1;" : "=l"(t64) : "l"(&h_buf[0][0]));
        hloc = (uint32_t)t64;
    }
    uint32_t hpeer;
    asm("mapa.shared::cluster.u32 %0, %1, %2;"
        : "=r"(hpeer) : "r"(hloc), "r"(rank ^ 1));

    const size_t zbase = (size_t)batch * S_LEN * H_DIM;

    float zc = 0.f, zn = 0.f;
    if (tid < 128) zc = Z[zbase + rank * 128 + tid];   // t = 0 prefetch

    asm volatile("barrier.cluster.arrive.aligned;" ::: "memory");
    asm volatile("barrier.cluster.wait.aligned;"   ::: "memory");

    for (int t = 0; t < S_LEN; t++) {
        const int cur = t & 1;
        const int nxt = cur ^ 1;

        // Partial dot products: warp-broadcast LDS.128 of h chunk
        const float4* h4 = reinterpret_cast<const float4*>(h_buf[cur]) + kc * 8;
        float a0 = 0.f, a1 = 0.f;
#pragma unroll
        for (int j = 0; j < 8; j++) {
            float4 hv = h4[j];
            a0 = fmaf(w0[j * 4 + 0], hv.x, a0);
            a0 = fmaf(w0[j * 4 + 1], hv.y, a0);
            a0 = fmaf(w0[j * 4 + 2], hv.z, a0);
            a0 = fmaf(w0[j * 4 + 3], hv.w, a0);
            a1 = fmaf(w1[j * 4 + 0], hv.x, a1);
            a1 = fmaf(w1[j * 4 + 1], hv.y, a1);
            a1 = fmaf(w1[j * 4 + 2], hv.z, a1);
            a1 = fmaf(w1[j * 4 + 3], hv.w, a1);
        }
        stage[ri][kc]      = a0;
        stage[ri + 64][kc] = a1;
        __syncthreads();

        if (tid < 128) {
            float s = zc;
#pragma unroll
            for (int j = 0; j < 8; j++) s += stage[tid][j];
            float hv = tanhf(s);
            const int gr = rank * 128 + tid;
            h_buf[nxt][gr] = hv;
            // mirror into peer's SMEM
            asm volatile("st.shared::cluster.f32 [%0], %1;"
                         :: "r"(hpeer + (uint32_t)((nxt * H_DIM + gr) * 4)),
                            "f"(hv) : "memory");
            Hout[zbase + (size_t)t * H_DIM + gr] = hv;
            if (t + 1 < S_LEN)
                zn = Z[zbase + (size_t)(t + 1) * H_DIM + gr];  // prefetch
        }

        // Publish DSMEM writes + step barrier for both CTAs
        asm volatile("barrier.cluster.arrive.aligned;" ::: "memory");
        asm volatile("barrier.cluster.wait.aligned;"   ::: "memory");
        zc = zn;
    }
}

// ---------------------------------------------------------------------------
extern "C" void kernel_launch(void* const* d_in, const int* in_sizes, int n_in,
                              void* d_out, int out_size)
{
    const float* x    = (const float*)d_in[0];
    const float* U0   = (const float*)d_in[1];
    const float* bU0  = (const float*)d_in[2];
    const float* W0   = (const float*)d_in[3];
    const float* bW0  = (const float*)d_in[4];
    const float* U1   = (const float*)d_in[5];
    const float* bU1  = (const float*)d_in[6];
    const float* W1   = (const float*)d_in[7];
    const float* bW1  = (const float*)d_in[8];
    const float* fc1W = (const float*)d_in[9];
    const float* fc1b = (const float*)d_in[10];
    const float* fc2W = (const float*)d_in[11];
    const float* fc2b = (const float*)d_in[12];
    const float* fc3W = (const float*)d_in[13];
    const float* fc3b = (const float*)d_in[14];
    float* out = (float*)d_out;

    float *bufA, *bufB, *bufC, *bufD;
    cudaGetSymbolAddress((void**)&bufA, g_bufA);
    cudaGetSymbolAddress((void**)&bufB, g_bufB);
    cudaGetSymbolAddress((void**)&bufC, g_bufC);
    cudaGetSymbolAddress((void**)&bufD, g_bufD);

    dim3 blk(256);
    dim3 g256(2, NROWS / 128);   // N = 256
    dim3 g64(1, NROWS / 128);    // N = 64

    // 1) Z0 = x @ U0^T + bU0 + bW0
    sgemm_bias<<<g256, blk>>>(x, U0, bU0, bW0, bufA, NROWS, H_DIM, I_DIM);
    // 2) scan layer 0 -> H0
    scan_rnn<<<128, 512>>>(bufA, W0, bufB);
    // 3) Z1 = H0 @ U1^T + bU1 + bW1
    sgemm_bias<<<g256, blk>>>(bufB, U1, bU1, bW1, bufC, NROWS, H_DIM, H_DIM);
    // 4) scan layer 1 -> H1 (= outs)
    scan_rnn<<<128, 512>>>(bufC, W1, bufD);
    // 5) head: fc1 -> fc2 -> fc3
    sgemm_bias<<<g256, blk>>>(bufD, fc1W, fc1b, nullptr, bufA, NROWS, H_DIM, H_DIM);
    sgemm_bias<<<g256, blk>>>(bufA, fc2W, fc2b, nullptr, bufB, NROWS, H_DIM, H_DIM);
    sgemm_bias<<<g64,  blk>>>(bufB, fc3W, fc3b, nullptr, out,  NROWS, O_DIM, H_DIM);
}

// round 5
// speedup vs baseline: 1.3888x; 1.3888x over previous
#include <cuda_runtime.h>
#include <cuda_bf16.h>
#include <cstdint>

#define S_LEN 2048
#define B_SZ  64
#define I_DIM 128
#define H_DIM 256
#define O_DIM 64
#define NROWS (S_LEN * B_SZ)   // 131072 rows, n = b*S + s

// Scratch (static device arrays: allocation-free rule).
__device__ float g_bufA[(size_t)NROWS * H_DIM];
__device__ float g_bufB[(size_t)NROWS * H_DIM];
__device__ float g_bufC[(size_t)NROWS * H_DIM];
__device__ float g_bufD[(size_t)NROWS * H_DIM];

// ---- packed fp32x2 helpers (sm_100+) --------------------------------------
__device__ __forceinline__ void fma2(unsigned long long& d,
                                     unsigned long long a,
                                     unsigned long long b)
{
    asm("fma.rn.f32x2 %0, %1, %2, %0;" : "+l"(d) : "l"(a), "l"(b));
}
__device__ __forceinline__ unsigned long long splat2(float x)
{
    unsigned long long r;
    asm("mov.b64 %0, {%1, %1};" : "=l"(r) : "f"(x));
    return r;
}
__device__ __forceinline__ float2 unpack2(unsigned long long v)
{
    float2 r;
    asm("mov.b64 {%0, %1}, %2;" : "=f"(r.x), "=f"(r.y) : "l"(v));
    return r;
}

// ---------------------------------------------------------------------------
// GEMM: C[M,N] = A[M,K] @ W[N,K]^T + b1[n] (+ b2[n])
// BM=128, BN=128, BK=16, TM=TN=8, 256 threads. fp32x2 packed accumulation
// (acc pairs along M; N-values splatted once per k).
// ---------------------------------------------------------------------------
__global__ __launch_bounds__(256, 2) void sgemm_bias(
    const float* __restrict__ A, const float* __restrict__ W,
    const float* __restrict__ b1, const float* __restrict__ b2,
    float* __restrict__ C, int M, int N, int K)
{
    constexpr int BM = 128, BN = 128, BK = 16, TM = 8, TN = 8;
    __shared__ __align__(16) float As[BK][BM + 4];
    __shared__ __align__(16) float Ws[BK][BN + 4];

    const int tid = threadIdx.x;
    const int tx  = tid & 15;   // n sub-tile
    const int ty  = tid >> 4;   // m sub-tile
    const int m0  = blockIdx.y * BM;
    const int n0  = blockIdx.x * BN;

    // acc2[p][j]: packed pair (row 2p, row 2p+1) for column j
    unsigned long long acc2[TM / 2][TN];
#pragma unroll
    for (int p = 0; p < TM / 2; p++)
#pragma unroll
        for (int j = 0; j < TN; j++) acc2[p][j] = 0ULL;

    for (int k0 = 0; k0 < K; k0 += BK) {
#pragma unroll
        for (int l = 0; l < 2; l++) {
            int idx = tid + l * 256;
            int r = idx >> 2;
            int c = (idx & 3) << 2;
            float4 v = *reinterpret_cast<const float4*>(
                A + (size_t)(m0 + r) * K + k0 + c);
            As[c + 0][r] = v.x; As[c + 1][r] = v.y;
            As[c + 2][r] = v.z; As[c + 3][r] = v.w;
        }
#pragma unroll
        for (int l = 0; l < 2; l++) {
            int idx = tid + l * 256;
            int r = idx >> 2;
            int c = (idx & 3) << 2;
            float4 v = make_float4(0.f, 0.f, 0.f, 0.f);
            if (n0 + r < N)
                v = *reinterpret_cast<const float4*>(
                    W + (size_t)(n0 + r) * K + k0 + c);
            Ws[c + 0][r] = v.x; Ws[c + 1][r] = v.y;
            Ws[c + 2][r] = v.z; Ws[c + 3][r] = v.w;
        }
        __syncthreads();

#pragma unroll
        for (int k = 0; k < BK; k++) {
            // m pairs come packed straight from shared memory
            ulonglong2 ra = *reinterpret_cast<const ulonglong2*>(&As[k][ty * TM]);
            ulonglong2 rb = *reinterpret_cast<const ulonglong2*>(&As[k][ty * TM + 4]);
            unsigned long long rm2[4] = { ra.x, ra.y, rb.x, rb.y };

            float4 n0v = *reinterpret_cast<const float4*>(&Ws[k][tx * TN]);
            float4 n1v = *reinterpret_cast<const float4*>(&Ws[k][tx * TN + 4]);
            unsigned long long rn2[TN];
            rn2[0] = splat2(n0v.x); rn2[1] = splat2(n0v.y);
            rn2[2] = splat2(n0v.z); rn2[3] = splat2(n0v.w);
            rn2[4] = splat2(n1v.x); rn2[5] = splat2(n1v.y);
            rn2[6] = splat2(n1v.z); rn2[7] = splat2(n1v.w);

#pragma unroll
            for (int p = 0; p < TM / 2; p++)
#pragma unroll
                for (int j = 0; j < TN; j++)
                    fma2(acc2[p][j], rm2[p], rn2[j]);
        }
        __syncthreads();
    }

    // Epilogue: unpack, bias add, store.
    const int gn0 = n0 + tx * TN;
    if (gn0 < N) {
        float bias[TN];
#pragma unroll
        for (int j = 0; j < TN; j++) {
            int gn = gn0 + j;
            bias[j] = b1[gn] + (b2 ? b2[gn] : 0.f);
        }
#pragma unroll
        for (int p = 0; p < TM / 2; p++) {
            float r0[TN], r1[TN];
#pragma unroll
            for (int j = 0; j < TN; j++) {
                float2 u = unpack2(acc2[p][j]);
                r0[j] = u.x + bias[j];
                r1[j] = u.y + bias[j];
            }
            int gm = m0 + ty * TM + 2 * p;
            float4 o;
            o = make_float4(r0[0], r0[1], r0[2], r0[3]);
            *reinterpret_cast<float4*>(C + (size_t)gm * N + gn0) = o;
            o = make_float4(r0[4], r0[5], r0[6], r0[7]);
            *reinterpret_cast<float4*>(C + (size_t)gm * N + gn0 + 4) = o;
            o = make_float4(r1[0], r1[1], r1[2], r1[3]);
            *reinterpret_cast<float4*>(C + (size_t)(gm + 1) * N + gn0) = o;
            o = make_float4(r1[4], r1[5], r1[6], r1[7]);
            *reinterpret_cast<float4*>(C + (size_t)(gm + 1) * N + gn0 + 4) = o;
        }
    }
}

// ---------------------------------------------------------------------------
// Recurrent scan: H[t] = tanh(Z[t] + W @ H[t-1]) per batch element.
// 2-CTA cluster per batch; W register-resident (packed fp32x2 pairs along k).
// Step sync: st.async (local+peer) completing on a per-CTA mbarrier;
// wait is acquire.cluster so peer st.async data is ordered.
// ---------------------------------------------------------------------------
__global__ void __cluster_dims__(2, 1, 1) __launch_bounds__(512, 1)
scan_rnn(const float* __restrict__ Z, const float* __restrict__ Wr,
         float* __restrict__ Hout)
{
    __shared__ __align__(16) float h_buf[2][H_DIM];
    __shared__ float stage[128][9];           // stride 9 -> conflict-free
    __shared__ __align__(8) unsigned long long mbar;

    const int tid = threadIdx.x;
    uint32_t rank_u;
    asm("mov.u32 %0, %%cluster_ctarank;" : "=r"(rank_u));
    const int rank  = (int)rank_u;
    const int batch = blockIdx.x >> 1;
    const int kc = tid >> 6;        // 0..7 (warp-uniform -> broadcast LDS)
    const int ri = tid & 63;        // 0..63
    const int row0 = rank * 128 + ri;
    const int row1 = row0 + 64;

    // W chunk packed as fp32x2 pairs along k: rows {row0,row1},
    // k in [kc*32, kc*32+32), CONTIGUOUS: 8 x ulonglong2 (4 floats each).
    // Pair layout matches h reads: w[2j] <-> k=4j,4j+1 ; w[2j+1] <-> 4j+2,4j+3.
    unsigned long long w0p[16], w1p[16];
#pragma unroll
    for (int j = 0; j < 8; j++) {
        ulonglong2 a = *reinterpret_cast<const ulonglong2*>(
            Wr + (size_t)row0 * H_DIM + kc * 32 + j * 4);
        w0p[j * 2 + 0] = a.x; w0p[j * 2 + 1] = a.y;
        ulonglong2 b = *reinterpret_cast<const ulonglong2*>(
            Wr + (size_t)row1 * H_DIM + kc * 32 + j * 4);
        w1p[j * 2 + 0] = b.x; w1p[j * 2 + 1] = b.y;
    }

    if (tid < H_DIM) { h_buf[0][tid] = 0.f; h_buf[1][tid] = 0.f; }
    if (tid == 0) {
        uint32_t mb;
        asm("{ .reg .u64 t; cvta.to.shared.u64 t, %1; cvt.u32.u64 %0, t; }"
            : "=r"(mb) : "l"(&mbar));
        asm volatile("mbarrier.init.shared.b64 [%0], 1;" :: "r"(mb) : "memory");
    }
    __syncthreads();

    // shared::cluster addresses for h_buf (self + peer) and mbar (self + peer)
    uint32_t hloc, mloc;
    asm("{ .reg .u64 t; cvta.to.shared.u64 t, %1; cvt.u32.u64 %0, t; }"
        : "=r"(hloc) : "l"(&h_buf[0][0]));
    asm("{ .reg .u64 t; cvta.to.shared.u64 t, %1; cvt.u32.u64 %0, t; }"
        : "=r"(mloc) : "l"(&mbar));
    uint32_t hself, hpeer, mself, mpeer;
    asm("mapa.shared::cluster.u32 %0, %1, %2;" : "=r"(hself) : "r"(hloc), "r"(rank));
    asm("mapa.shared::cluster.u32 %0, %1, %2;" : "=r"(hpeer) : "r"(hloc), "r"(rank ^ 1));
    asm("mapa.shared::cluster.u32 %0, %1, %2;" : "=r"(mself) : "r"(mloc), "r"(rank));
    asm("mapa.shared::cluster.u32 %0, %1, %2;" : "=r"(mpeer) : "r"(mloc), "r"(rank ^ 1));

    const size_t zbase = (size_t)batch * S_LEN * H_DIM;

    float zc = 0.f, zn = 0.f;
    if (tid < 128) zc = Z[zbase + rank * 128 + tid];   // t = 0 prefetch

    // mbarriers initialized in both CTAs before any st.async targets them
    asm volatile("barrier.cluster.arrive.aligned;" ::: "memory");
    asm volatile("barrier.cluster.wait.aligned;"   ::: "memory");

    for (int t = 0; t < S_LEN; t++) {
        const int cur = t & 1;
        const int nxt = cur ^ 1;

        // Arm this phase: 1 arrival (this op) + 1024 tx bytes
        // (512 from local writers + 512 from peer writers).
        if (tid == 0)
            asm volatile("mbarrier.arrive.expect_tx.shared.b64 _, [%0], 1024;"
                         :: "r"(mloc) : "memory");

        // Partial dot products: packed fp32x2, warp-broadcast loads of h
        const ulonglong2* h8 =
            reinterpret_cast<const ulonglong2*>(h_buf[cur] + kc * 32);
        unsigned long long a0p = 0ULL, a1p = 0ULL;
#pragma unroll
        for (int j = 0; j < 8; j++) {
            ulonglong2 hv = h8[j];
            fma2(a0p, w0p[j * 2 + 0], hv.x);
            fma2(a0p, w0p[j * 2 + 1], hv.y);
            fma2(a1p, w1p[j * 2 + 0], hv.x);
            fma2(a1p, w1p[j * 2 + 1], hv.y);
        }
        float2 u0 = unpack2(a0p);
        float2 u1 = unpack2(a1p);
        stage[ri][kc]      = u0.x + u0.y;
        stage[ri + 64][kc] = u1.x + u1.y;
        __syncthreads();

        if (tid < 128) {
            float s = zc;
#pragma unroll
            for (int j = 0; j < 8; j++) s += stage[tid][j];
            float hv = tanhf(s);
            const int gr = rank * 128 + tid;
            const uint32_t off = (uint32_t)((nxt * H_DIM + gr) * 4);
            // write h into BOTH CTAs' buffers, completing on each CTA's mbar
            asm volatile(
                "st.async.shared::cluster.mbarrier::complete_tx::bytes.b32 [%0], %1, [%2];"
                :: "r"(hself + off), "f"(hv), "r"(mself) : "memory");
            asm volatile(
                "st.async.shared::cluster.mbarrier::complete_tx::bytes.b32 [%0], %1, [%2];"
                :: "r"(hpeer + off), "f"(hv), "r"(mpeer) : "memory");
            Hout[zbase + (size_t)t * H_DIM + gr] = hv;
            if (t + 1 < S_LEN)
                zn = Z[zbase + (size_t)(t + 1) * H_DIM + gr];  // prefetch
        }

        // Wait for phase t: all 256 h values (local + peer) landed.
        // acquire at CLUSTER scope so peer st.async data is visible.
        {
            uint32_t done;
            asm volatile(
                "{\n\t.reg .pred p;\n\t"
                "mbarrier.try_wait.parity.acquire.cluster.shared::cta.b64 p, [%1], %2;\n\t"
                "selp.b32 %0, 1, 0, p;\n\t}"
                : "=r"(done) : "r"(mloc), "r"((uint32_t)(t & 1)) : "memory");
            if (!done) {
                asm volatile(
                    "{\n\t.reg .pred P1;\n\t"
                    "WL_%=:\n\t"
                    "mbarrier.try_wait.parity.acquire.cluster.shared::cta.b64 P1, [%0], %1, 0x989680;\n\t"
                    "@P1 bra.uni WD_%=;\n\t"
                    "bra.uni WL_%=;\n\t"
                    "WD_%=:\n\t}"
                    :: "r"(mloc), "r"((uint32_t)(t & 1)) : "memory");
            }
        }
        zc = zn;
    }

    // No CTA may exit while peer st.async traffic could still target it.
    asm volatile("barrier.cluster.arrive.aligned;" ::: "memory");
    asm volatile("barrier.cluster.wait.aligned;"   ::: "memory");
}

// ---------------------------------------------------------------------------
extern "C" void kernel_launch(void* const* d_in, const int* in_sizes, int n_in,
                              void* d_out, int out_size)
{
    const float* x    = (const float*)d_in[0];
    const float* U0   = (const float*)d_in[1];
    const float* bU0  = (const float*)d_in[2];
    const float* W0   = (const float*)d_in[3];
    const float* bW0  = (const float*)d_in[4];
    const float* U1   = (const float*)d_in[5];
    const float* bU1  = (const float*)d_in[6];
    const float* W1   = (const float*)d_in[7];
    const float* bW1  = (const float*)d_in[8];
    const float* fc1W = (const float*)d_in[9];
    const float* fc1b = (const float*)d_in[10];
    const float* fc2W = (const float*)d_in[11];
    const float* fc2b = (const float*)d_in[12];
    const float* fc3W = (const float*)d_in[13];
    const float* fc3b = (const float*)d_in[14];
    float* out = (float*)d_out;

    float *bufA, *bufB, *bufC, *bufD;
    cudaGetSymbolAddress((void**)&bufA, g_bufA);
    cudaGetSymbolAddress((void**)&bufB, g_bufB);
    cudaGetSymbolAddress((void**)&bufC, g_bufC);
    cudaGetSymbolAddress((void**)&bufD, g_bufD);

    dim3 blk(256);
    dim3 g256(2, NROWS / 128);   // N = 256
    dim3 g64(1, NROWS / 128);    // N = 64

    // 1) Z0 = x @ U0^T + bU0 + bW0
    sgemm_bias<<<g256, blk>>>(x, U0, bU0, bW0, bufA, NROWS, H_DIM, I_DIM);
    // 2) scan layer 0 -> H0
    scan_rnn<<<128, 512>>>(bufA, W0, bufB);
    // 3) Z1 = H0 @ U1^T + bU1 + bW1
    sgemm_bias<<<g256, blk>>>(bufB, U1, bU1, bW1, bufC, NROWS, H_DIM, H_DIM);
    // 4) scan layer 1 -> H1 (= outs)
    scan_rnn<<<128, 512>>>(bufC, W1, bufD);
    // 5) head: fc1 -> fc2 -> fc3
    sgemm_bias<<<g256, blk>>>(bufD, fc1W, fc1b, nullptr, bufA, NROWS, H_DIM, H_DIM);
    sgemm_bias<<<g256, blk>>>(bufA, fc2W, fc2b, nullptr, bufB, NROWS, H_DIM, H_DIM);
    sgemm_bias<<<g64,  blk>>>(bufB, fc3W, fc3b, nullptr, out,  NROWS, O_DIM, H_DIM);
}